// round 5
// baseline (speedup 1.0000x reference)
#include <cuda_runtime.h>
#include <math.h>

#define Bb 32
#define Tt 8
#define Nn 150
#define Ff 16
#define Hh 32
#define Rr 4
#define Ee 16

#define NP 160
#define NR 192
#define HSZ (Bb*Nn*Hh*Rr)

// slots: 0=f0, 1=Re f1, 2=Im f1, 3=f2, 4=slot1+slot2 (Karatsuba)
__device__ float g_At [5*NP*NR];          // adjacency transposed, padded
__device__ float g_W  [2*3*4*64*32];
__device__ float g_Xf [5*Tt*NP*512];      // fft slots of X, all t (GEMM input)
__device__ float g_AXt[5*Tt*Nn*512];      // A @ Xf, all t (precomputed)
__device__ float g_Hf [5*NP*2048];        // H slots: cols [0,1024)=H0, [1024,2048)=H1
__device__ float g_AH [5*Nn*2048];        // A @ Hf
__device__ float g_Gf [5*NP*2048];        // slots of Rg*Hs
__device__ float g_AG [5*Nn*2048];        // A @ Gf
__device__ float g_Z  [2*HSZ];
__device__ float g_H  [4*HSZ];

// ---------------------------------------------------------------------------
__global__ void adj_kernel(const float* __restrict__ U) {
    __shared__ float sUf[Ee][4];
    __shared__ float red[256];
    int n = blockIdx.x;
    int tid = threadIdx.x;
    if (tid < Ee*4) {
        int e = tid >> 2, s = tid & 3;
        const float* p = U + (n*Ee + e)*4;
        float u0=p[0],u1=p[1],u2=p[2],u3=p[3];
        float v;
        if (s==0) v = u0+u1+u2+u3;
        else if (s==1) v = u0-u2;
        else if (s==2) v = u3-u1;
        else v = u0-u1+u2-u3;
        sUf[e][s] = v;
    }
    __syncthreads();
    int m = tid;
    float a0=0.f,a1=0.f,a2=0.f,a3=0.f;
    if (m < Nn) {
        float P0=0.f,P1r=0.f,P1i=0.f,P2=0.f;
        #pragma unroll
        for (int e=0;e<Ee;e++){
            const float* p = U + (m*Ee + e)*4;
            float u0=p[0],u1=p[1],u2=p[2],u3=p[3];
            float m0=u0+u1+u2+u3, m1r=u0-u2, m1i=u3-u1, m2=u0-u1+u2-u3;
            float q0=sUf[e][0], q1r=sUf[e][1], q1i=sUf[e][2], q2=sUf[e][3];
            P0  += q0*m0;
            P2  += q2*m2;
            P1r += q1r*m1r - q1i*m1i;
            P1i += q1r*m1i + q1i*m1r;
        }
        a0 = fmaxf(0.25f*(P0 + P2 + 2.f*P1r), 0.f);
        a1 = fmaxf(0.25f*(P0 - P2 - 2.f*P1i), 0.f);
        a2 = fmaxf(0.25f*(P0 + P2 - 2.f*P1r), 0.f);
        a3 = fmaxf(0.25f*(P0 - P2 + 2.f*P1i), 0.f);
    }
    float av[4] = {a0,a1,a2,a3};
    float v[4];
    for (int r=0;r<4;r++){
        red[tid] = (m<Nn) ? av[r] : -1e30f; __syncthreads();
        for (int s=128;s>0;s>>=1){ if (tid<s) red[tid]=fmaxf(red[tid],red[tid+s]); __syncthreads(); }
        float mx = red[0]; __syncthreads();
        float ex = (m<Nn) ? expf(av[r]-mx) : 0.f;
        red[tid] = ex; __syncthreads();
        for (int s=128;s>0;s>>=1){ if (tid<s) red[tid]+=red[tid+s]; __syncthreads(); }
        float sm = red[0]; __syncthreads();
        v[r] = ex / sm;
    }
    if (m < Nn) {
        float s1 = v[0]-v[2];
        float s2 = v[3]-v[1];
        g_At[0*NP*NR + m*NR + n] = v[0]+v[1]+v[2]+v[3];
        g_At[1*NP*NR + m*NR + n] = s1;
        g_At[2*NP*NR + m*NR + n] = s2;
        g_At[3*NP*NR + m*NR + n] = v[0]-v[1]+v[2]-v[3];
        g_At[4*NP*NR + m*NR + n] = s1 + s2;
    }
}

// ---------------------------------------------------------------------------
__global__ void wprep_kernel(const float* wxz0,const float* wxr0,const float* wxh0,
                             const float* whz0,const float* whr0,
                             const float* wxz1,const float* wxr1,const float* wxh1,
                             const float* whz1,const float* whr1) {
    int idx = blockIdx.x*blockDim.x + threadIdx.x;
    if (idx >= 2*3*64*32) return;
    int h = idx & 31;
    int c = (idx >> 5) & 63;
    int g = (idx >> 11) % 3;
    int l = idx / (3*64*32);
    int Fin = l ? 32 : 16;
    int C = Fin + 32;
    float w[4] = {0.f,0.f,0.f,0.f};
    if (c < C) {
        bool xp = c < Fin;
        int row = xp ? c : (c - Fin);
        const float* src;
        if (l == 0)
            src = (g==0) ? (xp? wxz0: whz0) : (g==1) ? (xp? wxr0: whr0) : (xp? wxh0: whr0);
        else
            src = (g==0) ? (xp? wxz1: whz1) : (g==1) ? (xp? wxr1: whr1) : (xp? wxh1: whr1);
        const float* p = src + (row*Hh + h)*4;
        float u0=p[0],u1=p[1],u2=p[2],u3=p[3];
        w[0]=u0+u1+u2+u3; w[1]=u0-u2; w[2]=u3-u1; w[3]=u0-u1+u2-u3;
    }
    int base = ((l*3+g)*4)*2048 + c*32 + h;
    #pragma unroll
    for (int s=0;s<4;s++) g_W[base + s*2048] = w[s];
}

// ---------------------------------------------------------------------------
__global__ void xprep_kernel(const float* __restrict__ X){
    int idx = blockIdx.x*blockDim.x + threadIdx.x;
    if (idx >= Tt*Nn*512) return;
    int col = idx & 511;
    int rest = idx >> 9;
    int n = rest % Nn;
    int t = rest / Nn;
    int b = col >> 4, f = col & 15;
    const float4 v = *reinterpret_cast<const float4*>(
        X + ((((size_t)b*Tt + t)*Nn + n)*Ff + f)*4);
    float s1 = v.x - v.z, s2 = v.w - v.y;
    size_t base = ((size_t)t*NP + n)*512 + col;
    const size_t SS = (size_t)Tt*NP*512;
    g_Xf[0*SS + base] = v.x+v.y+v.z+v.w;
    g_Xf[1*SS + base] = s1;
    g_Xf[2*SS + base] = s2;
    g_Xf[3*SS + base] = v.x-v.y+v.z-v.w;
    g_Xf[4*SS + base] = s1 + s2;
}

// ---------------------------------------------------------------------------
// Aggregation GEMM: Out[s][plane] = A[s] @ B[s][plane].
// Tile 64x64, 256 threads, 4x4 per thread, double-buffered, K=160 (10x16).
// blockIdx.x -> (plane, colTile): plane = bx/planeBlocks, col = (bx%planeBlocks)*64
// ---------------------------------------------------------------------------
__global__ __launch_bounds__(256) void agg5_kernel(
    const float* __restrict__ B, int ldb, size_t sstB, size_t pStrB,
    float* __restrict__ O, int ldo, size_t sstO, size_t pStrO, int planeBlocks)
{
    int s = blockIdx.z;
    int p  = blockIdx.x / planeBlocks;
    int cb = (blockIdx.x - p*planeBlocks)*64;
    const float* Bp = B + (size_t)s*sstB + (size_t)p*pStrB + cb;
    float*       Op = O + (size_t)s*sstO + (size_t)p*pStrO + cb;
    int nBase = blockIdx.y*64;
    const float* A = g_At + (size_t)s*NP*NR + nBase;

    __shared__ float sA[2][16][64];
    __shared__ float sB[2][16][64];
    int tid = threadIdx.x;
    int tx = tid & 15, ty = tid >> 4;
    int lr = tid >> 4, lc = (tid & 15)*4;    // load: row 0..15, col*4

    const float* Ap = A + (size_t)lr*NR + lc;
    const float* Bq = Bp + (size_t)lr*ldb + lc;

    float4 ra = *reinterpret_cast<const float4*>(Ap);
    float4 rb = *reinterpret_cast<const float4*>(Bq);
    *reinterpret_cast<float4*>(&sA[0][lr][lc]) = ra;
    *reinterpret_cast<float4*>(&sB[0][lr][lc]) = rb;
    __syncthreads();

    float acc[4][4] = {};
    for (int ch=0; ch<10; ch++){
        int buf = ch&1;
        if (ch<9){
            size_t ko = (size_t)(ch+1)*16;
            ra = *reinterpret_cast<const float4*>(Ap + ko*NR);
            rb = *reinterpret_cast<const float4*>(Bq + ko*ldb);
        }
        #pragma unroll
        for (int kk=0;kk<16;kk++){
            float4 a = *reinterpret_cast<const float4*>(&sA[buf][kk][ty*4]);
            float4 b = *reinterpret_cast<const float4*>(&sB[buf][kk][tx*4]);
            float av[4]={a.x,a.y,a.z,a.w};
            float bv[4]={b.x,b.y,b.z,b.w};
            #pragma unroll
            for (int i=0;i<4;i++)
                #pragma unroll
                for (int j=0;j<4;j++)
                    acc[i][j] += av[i]*bv[j];
        }
        if (ch<9){
            int nb = buf^1;
            *reinterpret_cast<float4*>(&sA[nb][lr][lc]) = ra;
            *reinterpret_cast<float4*>(&sB[nb][lr][lc]) = rb;
        }
        __syncthreads();
    }
    #pragma unroll
    for (int i=0;i<4;i++){
        int n = nBase + ty*4 + i;
        if (n < Nn)
            *reinterpret_cast<float4*>(Op + (size_t)n*ldo + tx*4) =
                make_float4(acc[i][0],acc[i][1],acc[i][2],acc[i][3]);
    }
}

// ---------------------------------------------------------------------------
// Gates. block (32,4); thread = (h, bt) handles 8 batches.
// Reads X-part from precomputed AXt plane, H-part from g_AH.
// ---------------------------------------------------------------------------
__global__ void gates5_kernel(int secBase, const float* __restrict__ Xpl,
    const float* __restrict__ HsA, const float* __restrict__ biasA,
    const float* __restrict__ HsB, const float* __restrict__ biasB)
{
    int n = blockIdx.x;
    int sec = secBase + blockIdx.y;
    const float* Hs   = blockIdx.y ? HsB : HsA;
    const float* bias = blockIdx.y ? biasB : biasA;
    int C  = sec ? 64 : 48;
    int wb = sec ? 3*8192 : 0;
    int gcol = sec ? 1024 : 0;

    __shared__ float sX[4][64][33];
    int tid = threadIdx.y*32 + threadIdx.x;
    const size_t XS = (size_t)Tt*Nn*512;
    const size_t HSs = (size_t)Nn*2048;
    const float* Xrow = Xpl + (size_t)n*512;
    const float* Hrow = g_AH + (size_t)n*2048;
    for (int i=tid;i<4*C*32;i+=128){
        int c = i % C; int sb = i / C; int s = sb >> 5; int b = sb & 31;
        const float* ptr; size_t ss;
        if (sec==0){
            if (c<16){ ptr = Xrow + b*16 + c; ss = XS; }
            else     { ptr = Hrow + b*32 + (c-16); ss = HSs; }
        } else {
            ptr = Hrow + ((c<32)? (b*32+c) : (1024 + b*32 + (c-32)));
            ss = HSs;
        }
        float v;
        if (s==0)      v = ptr[0];
        else if (s==1) v = ptr[ss] - ptr[2*ss];
        else if (s==2) v = ptr[4*ss] - ptr[ss] - ptr[2*ss];
        else           v = ptr[3*ss];
        sX[s][c][b] = v;
    }
    __syncthreads();

    int h = threadIdx.x, bt = threadIdx.y;
    const float* Wz = g_W + wb;
    const float* Wr = Wz + 4*2048;
    float yz0[8]={},yz1[8]={},yz2[8]={},yz3[8]={};
    float yr0[8]={},yr1[8]={},yr2[8]={},yr3[8]={};
    for (int c=0;c<C;c++){
        int wo = c*32 + h;
        float wz0=Wz[wo],wz1=Wz[2048+wo],wz2=Wz[4096+wo],wz3=Wz[6144+wo];
        float wr0=Wr[wo],wr1=Wr[2048+wo],wr2=Wr[4096+wo],wr3=Wr[6144+wo];
        #pragma unroll
        for (int bb=0;bb<8;bb++){
            int b = bt*8+bb;
            float x0=sX[0][c][b], x1r=sX[1][c][b], x1i=sX[2][c][b], x2=sX[3][c][b];
            yz0[bb] += x0*wz0;
            yz1[bb] += x1r*wz1 - x1i*wz2;
            yz2[bb] += x1r*wz2 + x1i*wz1;
            yz3[bb] += x2*wz3;
            yr0[bb] += x0*wr0;
            yr1[bb] += x1r*wr1 - x1i*wr2;
            yr2[bb] += x1r*wr2 + x1i*wr1;
            yr3[bb] += x2*wr3;
        }
    }
    float bz[4], br[4];
    #pragma unroll
    for (int r=0;r<4;r++){ bz[r]=bias[h*4+r]; br[r]=bias[128+h*4+r]; }
    float* Z = g_Z + (size_t)sec*HSZ;
    const size_t GS = (size_t)NP*2048;
    #pragma unroll
    for (int bb=0;bb<8;bb++){
        int b = bt*8+bb;
        float vz[4] = {0.25f*(yz0[bb]+yz3[bb]+2.f*yz1[bb]), 0.25f*(yz0[bb]-yz3[bb]-2.f*yz2[bb]),
                       0.25f*(yz0[bb]+yz3[bb]-2.f*yz1[bb]), 0.25f*(yz0[bb]-yz3[bb]+2.f*yz2[bb])};
        float vr[4] = {0.25f*(yr0[bb]+yr3[bb]+2.f*yr1[bb]), 0.25f*(yr0[bb]-yr3[bb]-2.f*yr2[bb]),
                       0.25f*(yr0[bb]+yr3[bb]-2.f*yr1[bb]), 0.25f*(yr0[bb]-yr3[bb]+2.f*yr2[bb])};
        size_t hoff = (((size_t)b*Nn + n)*Hh + h)*4;
        float4 hs4 = Hs ? *reinterpret_cast<const float4*>(Hs + hoff) : make_float4(0,0,0,0);
        float hsv[4] = {hs4.x,hs4.y,hs4.z,hs4.w};
        float g[4], zv[4];
        #pragma unroll
        for (int r=0;r<4;r++){
            zv[r] = 1.f/(1.f+expf(-(vz[r] + bz[r])));
            float rg = 1.f/(1.f+expf(-(vr[r] + br[r])));
            g[r] = rg*hsv[r];
        }
        *reinterpret_cast<float4*>(Z + hoff) = make_float4(zv[0],zv[1],zv[2],zv[3]);
        size_t gb = (size_t)n*2048 + gcol + b*Hh + h;
        float s1 = g[0]-g[2], s2 = g[3]-g[1];
        g_Gf[0*GS + gb] = g[0]+g[1]+g[2]+g[3];
        g_Gf[1*GS + gb] = s1;
        g_Gf[2*GS + gb] = s2;
        g_Gf[3*GS + gb] = g[0]-g[1]+g[2]-g[3];
        g_Gf[4*GS + gb] = s1 + s2;
    }
}

// ---------------------------------------------------------------------------
// Ht + hidden update; writes new H (real), its slot-fft into g_Hf, out/tail.
// ---------------------------------------------------------------------------
__global__ void ht5_kernel(int secBase, int t, const float* __restrict__ Xpl,
    const float* __restrict__ HsA, const float* __restrict__ biasA,
    float* __restrict__ HnewA, float* __restrict__ outA, float* __restrict__ tailA,
    const float* __restrict__ HsB, const float* __restrict__ biasB,
    float* __restrict__ HnewB, float* __restrict__ outB, float* __restrict__ tailB)
{
    int n = blockIdx.x;
    int sec = secBase + blockIdx.y;
    const float* Hs   = blockIdx.y ? HsB : HsA;
    const float* bias = blockIdx.y ? biasB : biasA;
    float* Hnew = blockIdx.y ? HnewB : HnewA;
    float* outp = blockIdx.y ? outB : outA;
    float* tailp= blockIdx.y ? tailB : tailA;
    int Fin  = sec ? 32 : 16;
    int wb   = sec ? 5*8192 : 2*8192;
    int gcol = sec ? 1024 : 0;
    int hbase= sec ? 1024 : 0;

    __shared__ float sXx[4][32][33];
    __shared__ float sG[4][32][33];
    int tid = threadIdx.y*32 + threadIdx.x;
    const size_t XS = (size_t)Tt*Nn*512;
    const size_t HSs = (size_t)Nn*2048;
    const size_t AS = (size_t)Nn*2048;
    const float* Xrow = Xpl + (size_t)n*512;
    const float* Hrow = g_AH + (size_t)n*2048;
    const float* AG = g_AG + (size_t)n*2048 + gcol;
    for (int i=tid;i<4*Fin*32;i+=128){
        int c = i % Fin; int sb = i / Fin; int s = sb >> 5; int b = sb & 31;
        const float* ptr; size_t ss;
        if (sec==0){ ptr = Xrow + b*16 + c; ss = XS; }
        else       { ptr = Hrow + b*32 + c; ss = HSs; }
        float v;
        if (s==0)      v = ptr[0];
        else if (s==1) v = ptr[ss] - ptr[2*ss];
        else if (s==2) v = ptr[4*ss] - ptr[ss] - ptr[2*ss];
        else           v = ptr[3*ss];
        sXx[s][c][b] = v;
    }
    for (int i=tid;i<4*32*32;i+=128){
        int c = i & 31; int sb = i >> 5; int s = sb >> 5; int b = sb & 31;
        int col = b*Hh + c;
        float v;
        if (s==0)      v = AG[col];
        else if (s==1) v = AG[AS+col] - AG[2*AS+col];
        else if (s==2) v = AG[4*AS+col] - AG[AS+col] - AG[2*AS+col];
        else           v = AG[3*AS+col];
        sG[s][c][b] = v;
    }
    __syncthreads();

    int h = threadIdx.x, bt = threadIdx.y;
    const float* Wh = g_W + wb;
    float y0[8]={},y1[8]={},y2[8]={},y3[8]={};
    for (int c=0;c<Fin;c++){
        int wo = c*32 + h;
        float w0=Wh[wo],w1=Wh[2048+wo],w2=Wh[4096+wo],w3=Wh[6144+wo];
        #pragma unroll
        for (int bb=0;bb<8;bb++){
            int b = bt*8+bb;
            float x0=sXx[0][c][b], x1r=sXx[1][c][b], x1i=sXx[2][c][b], x2=sXx[3][c][b];
            y0[bb] += x0*w0;
            y1[bb] += x1r*w1 - x1i*w2;
            y2[bb] += x1r*w2 + x1i*w1;
            y3[bb] += x2*w3;
        }
    }
    for (int c=0;c<Hh;c++){
        int wo = (Fin+c)*32 + h;
        float w0=Wh[wo],w1=Wh[2048+wo],w2=Wh[4096+wo],w3=Wh[6144+wo];
        #pragma unroll
        for (int bb=0;bb<8;bb++){
            int b = bt*8+bb;
            float x0=sG[0][c][b], x1r=sG[1][c][b], x1i=sG[2][c][b], x2=sG[3][c][b];
            y0[bb] += x0*w0;
            y1[bb] += x1r*w1 - x1i*w2;
            y2[bb] += x1r*w2 + x1i*w1;
            y3[bb] += x2*w3;
        }
    }
    float bh[4];
    #pragma unroll
    for (int r=0;r<4;r++) bh[r] = bias[256 + h*4 + r];
    const float* Z = g_Z + (size_t)sec*HSZ;
    const size_t HS2 = (size_t)NP*2048;
    #pragma unroll
    for (int bb=0;bb<8;bb++){
        int b = bt*8+bb;
        float v[4] = {0.25f*(y0[bb]+y3[bb]+2.f*y1[bb]), 0.25f*(y0[bb]-y3[bb]-2.f*y2[bb]),
                      0.25f*(y0[bb]+y3[bb]-2.f*y1[bb]), 0.25f*(y0[bb]-y3[bb]+2.f*y2[bb])};
        size_t hoff = (((size_t)b*Nn+n)*Hh + h)*4;
        float4 z4 = *reinterpret_cast<const float4*>(Z + hoff);
        float zv[4] = {z4.x,z4.y,z4.z,z4.w};
        float4 hs4 = Hs ? *reinterpret_cast<const float4*>(Hs + hoff) : make_float4(0,0,0,0);
        float hsv[4] = {hs4.x,hs4.y,hs4.z,hs4.w};
        float hn[4];
        #pragma unroll
        for (int r=0;r<4;r++){
            float ht = tanhf(v[r] + bh[r]);
            hn[r] = zv[r]*hsv[r] + (1.f-zv[r])*ht;
        }
        float4 hv = make_float4(hn[0],hn[1],hn[2],hn[3]);
        *reinterpret_cast<float4*>(Hnew + hoff) = hv;
        if (outp)
            *reinterpret_cast<float4*>(outp + (((size_t)b*Tt + t)*Nn + n)*(Hh*4) + h*4) = hv;
        if (tailp)
            *reinterpret_cast<float4*>(tailp + hoff) = hv;
        size_t hb = (size_t)n*2048 + hbase + b*Hh + h;
        float s1 = hn[0]-hn[2], s2 = hn[3]-hn[1];
        g_Hf[0*HS2 + hb] = hn[0]+hn[1]+hn[2]+hn[3];
        g_Hf[1*HS2 + hb] = s1;
        g_Hf[2*HS2 + hb] = s2;
        g_Hf[3*HS2 + hb] = hn[0]-hn[1]+hn[2]-hn[3];
        g_Hf[4*HS2 + hb] = s1 + s2;
    }
}

// ---------------------------------------------------------------------------
extern "C" void kernel_launch(void* const* d_in, const int* in_sizes, int n_in,
                              void* d_out, int out_size) {
    (void)in_sizes; (void)n_in;
    const float* inputs = (const float*)d_in[0];
    const float* U      = (const float*)d_in[1];
    const float* B0p    = (const float*)d_in[7];
    const float* B1p    = (const float*)d_in[13];
    float* out = (float*)d_out;
    const int OUTSZ = Bb*Tt*Nn*Hh*Rr;
    float* tail = (out_size >= OUTSZ + 2*HSZ) ? (out + OUTSZ) : nullptr;

    void* p;
    cudaGetSymbolAddress(&p, g_At);  float* Atp  = (float*)p;
    cudaGetSymbolAddress(&p, g_Xf);  float* Xf   = (float*)p;
    cudaGetSymbolAddress(&p, g_AXt); float* AXt  = (float*)p;
    cudaGetSymbolAddress(&p, g_Hf);  float* Hf   = (float*)p;
    cudaGetSymbolAddress(&p, g_AH);  float* AH   = (float*)p;
    cudaGetSymbolAddress(&p, g_Gf);  float* Gfp  = (float*)p;
    cudaGetSymbolAddress(&p, g_AG);  float* AG   = (float*)p;
    cudaGetSymbolAddress(&p, g_H);   float* Hb   = (float*)p;
    float* H0[2] = {Hb,          Hb +   HSZ};
    float* H1[2] = {Hb + 2*HSZ,  Hb + 3*HSZ};

    cudaMemsetAsync(Atp, 0, sizeof(float)*5*NP*NR);
    cudaMemsetAsync(Xf,  0, sizeof(float)*5*Tt*NP*512);
    cudaMemsetAsync(Hf,  0, sizeof(float)*5*NP*2048);
    cudaMemsetAsync(Gfp, 0, sizeof(float)*5*NP*2048);
    cudaMemsetAsync(AH,  0, sizeof(float)*5*Nn*2048);
    cudaMemsetAsync(AG,  0, sizeof(float)*5*Nn*2048);

    adj_kernel<<<Nn, 256>>>(U);
    wprep_kernel<<<48, 256>>>((const float*)d_in[2], (const float*)d_in[3], (const float*)d_in[4],
                              (const float*)d_in[5], (const float*)d_in[6],
                              (const float*)d_in[8], (const float*)d_in[9], (const float*)d_in[10],
                              (const float*)d_in[11], (const float*)d_in[12]);
    xprep_kernel<<<(Tt*Nn*512+255)/256, 256>>>(inputs);

    // Precompute A @ fft(X_t) for ALL timesteps in one batched launch
    agg5_kernel<<<dim3(Tt*8,3,5), 256>>>(
        Xf, 512, (size_t)Tt*NP*512, (size_t)NP*512,
        AXt, 512, (size_t)Tt*Nn*512, (size_t)Nn*512, 8);

    const size_t HB_SST = (size_t)NP*2048;
    const size_t HO_SST = (size_t)Nn*2048;
    dim3 blk128(32,4);

    // ---- t = 0, layer0 (H terms zero) ----
    gates5_kernel<<<dim3(Nn,1), blk128>>>(0, AXt, nullptr, B0p, nullptr, B0p);
    ht5_kernel<<<dim3(Nn,1), blk128>>>(0, 0, AXt,
        nullptr, B0p, H0[1], nullptr, nullptr,
        nullptr, B0p, H0[1], nullptr, nullptr);
    // A @ fft(H0(t0)) for layer1 (H0 columns only)
    agg5_kernel<<<dim3(16,3,5), 256>>>(Hf, 2048, HB_SST, 0, AH, 2048, HO_SST, 0, 16);
    gates5_kernel<<<dim3(Nn,1), blk128>>>(1, AXt, nullptr, B1p, nullptr, B1p);
    ht5_kernel<<<dim3(Nn,1), blk128>>>(1, 0, AXt,
        nullptr, B1p, H1[1], out, nullptr,
        nullptr, B1p, H1[1], out, nullptr);

    // ---- t = 1..7 ----
    int c0 = 1, c1 = 1;
    for (int t=1; t<Tt; t++){
        float* tl0 = (t==Tt-1 && tail) ? tail        : nullptr;
        float* tl1 = (t==Tt-1 && tail) ? tail + HSZ  : nullptr;
        const float* Xpl = AXt + (size_t)t*Nn*512;
        agg5_kernel<<<dim3(32,3,5), 256>>>(Hf, 2048, HB_SST, 0, AH, 2048, HO_SST, 0, 32);
        gates5_kernel<<<dim3(Nn,2), blk128>>>(0, Xpl, H0[c0], B0p, H1[c1], B1p);
        agg5_kernel<<<dim3(32,3,5), 256>>>(Gfp, 2048, HB_SST, 0, AG, 2048, HO_SST, 0, 32);
        ht5_kernel<<<dim3(Nn,2), blk128>>>(0, t, Xpl,
            H0[c0], B0p, H0[c0^1], nullptr, tl0,
            H1[c1], B1p, H1[c1^1], out,     tl1);
        c0 ^= 1; c1 ^= 1;
    }
}

// round 6
// speedup vs baseline: 1.0105x; 1.0105x over previous
#include <cuda_runtime.h>
#include <math.h>

#define Bb 32
#define Tt 8
#define Nn 150
#define Ff 16
#define Hh 32
#define Rr 4
#define Ee 16

#define NP 160
#define NR 192
#define HSZ (Bb*Nn*Hh*Rr)
#define GRID 296

// slots: 0=f0, 1=Re f1, 2=Im f1, 3=f2, 4=slot1+slot2 (Karatsuba)
__device__ float g_At [5*NP*NR];
__device__ float g_W  [2*3*64*128];       // [gateBlk(6)][c(64)][h(32)][slot(4)] as float4
__device__ float g_Xf [5*Tt*NP*512];
__device__ float g_AXt[5*Tt*Nn*512];
__device__ float g_Hf [5*NP*2048];        // cols [0,1024)=H0, [1024,2048)=H1
__device__ float g_AH [5*Nn*2048];
__device__ float g_Gf [5*NP*2048];
__device__ float g_AG [5*Nn*2048];
__device__ float g_Z  [2*HSZ];
__device__ float g_H  [4*HSZ];
__device__ unsigned long long g_barCnt;

// ---------------------------------------------------------------------------
__global__ void adj_kernel(const float* __restrict__ U) {
    __shared__ float sUf[Ee][4];
    __shared__ float red[256];
    int n = blockIdx.x;
    int tid = threadIdx.x;
    if (tid < Ee*4) {
        int e = tid >> 2, s = tid & 3;
        const float* p = U + (n*Ee + e)*4;
        float u0=p[0],u1=p[1],u2=p[2],u3=p[3];
        float v;
        if (s==0) v = u0+u1+u2+u3;
        else if (s==1) v = u0-u2;
        else if (s==2) v = u3-u1;
        else v = u0-u1+u2-u3;
        sUf[e][s] = v;
    }
    __syncthreads();
    int m = tid;
    float a0=0.f,a1=0.f,a2=0.f,a3=0.f;
    if (m < Nn) {
        float P0=0.f,P1r=0.f,P1i=0.f,P2=0.f;
        #pragma unroll
        for (int e=0;e<Ee;e++){
            const float* p = U + (m*Ee + e)*4;
            float u0=p[0],u1=p[1],u2=p[2],u3=p[3];
            float m0=u0+u1+u2+u3, m1r=u0-u2, m1i=u3-u1, m2=u0-u1+u2-u3;
            float q0=sUf[e][0], q1r=sUf[e][1], q1i=sUf[e][2], q2=sUf[e][3];
            P0  += q0*m0;
            P2  += q2*m2;
            P1r += q1r*m1r - q1i*m1i;
            P1i += q1r*m1i + q1i*m1r;
        }
        a0 = fmaxf(0.25f*(P0 + P2 + 2.f*P1r), 0.f);
        a1 = fmaxf(0.25f*(P0 - P2 - 2.f*P1i), 0.f);
        a2 = fmaxf(0.25f*(P0 + P2 - 2.f*P1r), 0.f);
        a3 = fmaxf(0.25f*(P0 - P2 + 2.f*P1i), 0.f);
    }
    float av[4] = {a0,a1,a2,a3};
    float v[4];
    for (int r=0;r<4;r++){
        red[tid] = (m<Nn) ? av[r] : -1e30f; __syncthreads();
        for (int s=128;s>0;s>>=1){ if (tid<s) red[tid]=fmaxf(red[tid],red[tid+s]); __syncthreads(); }
        float mx = red[0]; __syncthreads();
        float ex = (m<Nn) ? expf(av[r]-mx) : 0.f;
        red[tid] = ex; __syncthreads();
        for (int s=128;s>0;s>>=1){ if (tid<s) red[tid]+=red[tid+s]; __syncthreads(); }
        float sm = red[0]; __syncthreads();
        v[r] = ex / sm;
    }
    if (m < Nn) {
        float s1 = v[0]-v[2];
        float s2 = v[3]-v[1];
        g_At[0*NP*NR + m*NR + n] = v[0]+v[1]+v[2]+v[3];
        g_At[1*NP*NR + m*NR + n] = s1;
        g_At[2*NP*NR + m*NR + n] = s2;
        g_At[3*NP*NR + m*NR + n] = v[0]-v[1]+v[2]-v[3];
        g_At[4*NP*NR + m*NR + n] = s1 + s2;
    }
}

// ---------------------------------------------------------------------------
__global__ void wprep_kernel(const float* wxz0,const float* wxr0,const float* wxh0,
                             const float* whz0,const float* whr0,
                             const float* wxz1,const float* wxr1,const float* wxh1,
                             const float* whz1,const float* whr1) {
    int idx = blockIdx.x*blockDim.x + threadIdx.x;
    if (idx >= 2*3*64*32) return;
    int h = idx & 31;
    int c = (idx >> 5) & 63;
    int g = (idx >> 11) % 3;
    int l = idx / (3*64*32);
    int Fin = l ? 32 : 16;
    int C = Fin + 32;
    float w[4] = {0.f,0.f,0.f,0.f};
    if (c < C) {
        bool xp = c < Fin;
        int row = xp ? c : (c - Fin);
        const float* src;
        if (l == 0)
            src = (g==0) ? (xp? wxz0: whz0) : (g==1) ? (xp? wxr0: whr0) : (xp? wxh0: whr0);
        else
            src = (g==0) ? (xp? wxz1: whz1) : (g==1) ? (xp? wxr1: whr1) : (xp? wxh1: whr1);
        const float* p = src + (row*Hh + h)*4;
        float u0=p[0],u1=p[1],u2=p[2],u3=p[3];
        w[0]=u0+u1+u2+u3; w[1]=u0-u2; w[2]=u3-u1; w[3]=u0-u1+u2-u3;
    }
    int base = ((l*3+g)*64 + c)*128 + h*4;
    #pragma unroll
    for (int s=0;s<4;s++) g_W[base + s] = w[s];
}

// ---------------------------------------------------------------------------
__global__ void xprep_kernel(const float* __restrict__ X){
    int idx = blockIdx.x*blockDim.x + threadIdx.x;
    if (idx >= Tt*Nn*512) return;
    int col = idx & 511;
    int rest = idx >> 9;
    int n = rest % Nn;
    int t = rest / Nn;
    int b = col >> 4, f = col & 15;
    const float4 v = *reinterpret_cast<const float4*>(
        X + ((((size_t)b*Tt + t)*Nn + n)*Ff + f)*4);
    float s1 = v.x - v.z, s2 = v.w - v.y;
    size_t base = ((size_t)t*NP + n)*512 + col;
    const size_t SS = (size_t)Tt*NP*512;
    g_Xf[0*SS + base] = v.x+v.y+v.z+v.w;
    g_Xf[1*SS + base] = s1;
    g_Xf[2*SS + base] = s2;
    g_Xf[3*SS + base] = v.x-v.y+v.z-v.w;
    g_Xf[4*SS + base] = s1 + s2;
}

// ---------------------------------------------------------------------------
// Standalone batched agg for the X precompute (all timesteps at once).
// ---------------------------------------------------------------------------
__global__ __launch_bounds__(256) void aggx_kernel()
{
    int s = blockIdx.z;
    int p  = blockIdx.x >> 3;          // timestep
    int cb = (blockIdx.x & 7)*64;
    const float* Bp = g_Xf + (size_t)s*Tt*NP*512 + (size_t)p*NP*512 + cb;
    float*       Op = g_AXt + (size_t)s*Tt*Nn*512 + (size_t)p*Nn*512 + cb;
    int nBase = blockIdx.y*64;
    const float* A = g_At + (size_t)s*NP*NR + nBase;

    __shared__ float sA[2][16][64];
    __shared__ float sB[2][16][64];
    int tid = threadIdx.x;
    int tx = tid & 15, ty = tid >> 4;
    int lr = tid >> 4, lc = (tid & 15)*4;

    const float* Ap = A + (size_t)lr*NR + lc;
    const float* Bq = Bp + (size_t)lr*512 + lc;

    float4 ra = *reinterpret_cast<const float4*>(Ap);
    float4 rb = *reinterpret_cast<const float4*>(Bq);
    *reinterpret_cast<float4*>(&sA[0][lr][lc]) = ra;
    *reinterpret_cast<float4*>(&sB[0][lr][lc]) = rb;
    __syncthreads();

    float acc[4][4] = {};
    for (int ch=0; ch<10; ch++){
        int buf = ch&1;
        if (ch<9){
            size_t ko = (size_t)(ch+1)*16;
            ra = *reinterpret_cast<const float4*>(Ap + ko*NR);
            rb = *reinterpret_cast<const float4*>(Bq + ko*512);
        }
        #pragma unroll
        for (int kk=0;kk<16;kk++){
            float4 a = *reinterpret_cast<const float4*>(&sA[buf][kk][ty*4]);
            float4 b = *reinterpret_cast<const float4*>(&sB[buf][kk][tx*4]);
            float av[4]={a.x,a.y,a.z,a.w};
            float bv[4]={b.x,b.y,b.z,b.w};
            #pragma unroll
            for (int i=0;i<4;i++)
                #pragma unroll
                for (int j=0;j<4;j++)
                    acc[i][j] += av[i]*bv[j];
        }
        if (ch<9){
            int nb = buf^1;
            *reinterpret_cast<float4*>(&sA[nb][lr][lc]) = ra;
            *reinterpret_cast<float4*>(&sB[nb][lr][lc]) = rb;
        }
        __syncthreads();
    }
    #pragma unroll
    for (int i=0;i<4;i++){
        int n = nBase + ty*4 + i;
        if (n < Nn)
            *reinterpret_cast<float4*>(Op + (size_t)n*512 + tx*4) =
                make_float4(acc[i][0],acc[i][1],acc[i][2],acc[i][3]);
    }
}

// ===========================================================================
// Persistent fused kernel
// ===========================================================================
__device__ __forceinline__ void gridSync(unsigned long long target){
    __syncthreads();
    if (threadIdx.x == 0){
        __threadfence();
        atomicAdd(&g_barCnt, 1ULL);
        while (*((volatile unsigned long long*)&g_barCnt) < target)
            __nanosleep(64);
        __threadfence();
    }
    __syncthreads();
}

// Aggregation phase: Out[s] = At[s] @ B[s] over (colTiles x 64) columns.
__device__ void aggPhase(float* sm, const float* __restrict__ Bsrc,
                         float* __restrict__ Osrc, int colTiles, int colOff)
{
    float* sA = sm;            // [2][16][64]
    float* sB = sm + 2048;
    int tid = threadIdx.x;
    int tx = tid & 15, ty = tid >> 4;
    int lr = tid >> 4, lc = (tid & 15)*4;
    int perS = 3*colTiles;
    int total = 5*perS;
    for (int tile = blockIdx.x; tile < total; tile += gridDim.x){
        int s = tile / perS;
        int rem = tile - s*perS;
        int rt = rem / colTiles;
        int ct = rem - rt*colTiles;
        const float* Ap = g_At + (size_t)s*NP*NR + rt*64 + (size_t)lr*NR + lc;
        const float* Bq = Bsrc + (size_t)s*NP*2048 + colOff + ct*64 + (size_t)lr*2048 + lc;
        float* Op = Osrc + (size_t)s*Nn*2048 + colOff + ct*64;
        __syncthreads();
        float4 ra = *reinterpret_cast<const float4*>(Ap);
        float4 rb = *reinterpret_cast<const float4*>(Bq);
        *reinterpret_cast<float4*>(&sA[0*1024 + lr*64 + lc]) = ra;
        *reinterpret_cast<float4*>(&sB[0*1024 + lr*64 + lc]) = rb;
        __syncthreads();
        float acc[4][4] = {};
        for (int ch=0; ch<10; ch++){
            int buf = ch&1;
            if (ch<9){
                size_t ko = (size_t)(ch+1)*16;
                ra = *reinterpret_cast<const float4*>(Ap + ko*NR);
                rb = *reinterpret_cast<const float4*>(Bq + ko*2048);
            }
            #pragma unroll
            for (int kk=0;kk<16;kk++){
                float4 a = *reinterpret_cast<const float4*>(&sA[buf*1024 + kk*64 + ty*4]);
                float4 b = *reinterpret_cast<const float4*>(&sB[buf*1024 + kk*64 + tx*4]);
                float av[4]={a.x,a.y,a.z,a.w};
                float bv[4]={b.x,b.y,b.z,b.w};
                #pragma unroll
                for (int i=0;i<4;i++)
                    #pragma unroll
                    for (int j=0;j<4;j++)
                        acc[i][j] += av[i]*bv[j];
            }
            if (ch<9){
                int nb = (ch&1)^1;
                *reinterpret_cast<float4*>(&sA[nb*1024 + lr*64 + lc]) = ra;
                *reinterpret_cast<float4*>(&sB[nb*1024 + lr*64 + lc]) = rb;
            }
            __syncthreads();
        }
        int nBase = rt*64;
        #pragma unroll
        for (int i=0;i<4;i++){
            int n = nBase + ty*4 + i;
            if (n < Nn)
                *reinterpret_cast<float4*>(Op + (size_t)n*2048 + tx*4) =
                    make_float4(acc[i][0],acc[i][1],acc[i][2],acc[i][3]);
        }
    }
}

// Gates phase.
__device__ void gatesPhase(float* sm, int nItems, int secBase, const float* __restrict__ Xpl,
    const float* __restrict__ HsA, const float* __restrict__ HsB,
    const float* __restrict__ biasA, const float* __restrict__ biasB)
{
    int tid = threadIdx.x;
    const size_t XS = (size_t)Tt*Nn*512;
    const size_t HSs = (size_t)Nn*2048;
    const size_t GS = (size_t)NP*2048;
    for (int item = blockIdx.x; item < nItems; item += gridDim.x){
        int selB = (item >= Nn) ? 1 : 0;
        int n = item - selB*Nn;
        int sec = secBase + selB;
        const float* Hs   = selB ? HsB : HsA;
        const float* bias = selB ? biasB : biasA;
        int C    = sec ? 64 : 48;
        int gcol = sec ? 1024 : 0;
        const float* Xrow = Xpl + (size_t)n*512;
        const float* Hrow = g_AH + (size_t)n*2048;
        __syncthreads();
        for (int i=tid; i<4*64*32; i+=256){
            int c = i & 63; int sb = i >> 6; int s = sb >> 5; int b = sb & 31;
            float v = 0.f;
            if (c < C){
                const float* ptr; size_t ss;
                if (sec==0){
                    if (c<16){ ptr = Xrow + b*16 + c; ss = XS; }
                    else     { ptr = Hrow + b*32 + (c-16); ss = HSs; }
                } else {
                    ptr = Hrow + ((c<32)? (b*32+c) : (1024 + b*32 + (c-32)));
                    ss = HSs;
                }
                if (s==0)      v = ptr[0];
                else if (s==1) v = ptr[ss] - ptr[2*ss];
                else if (s==2) v = ptr[4*ss] - ptr[ss] - ptr[2*ss];
                else           v = ptr[3*ss];
            }
            sm[(s*32 + b)*64 + c] = v;
        }
        __syncthreads();
        int h = tid & 31, bt = tid >> 5;
        const float4* W4 = reinterpret_cast<const float4*>(g_W);
        const float4* Wz = W4 + (size_t)(sec*3+0)*64*32 + h;
        const float4* Wr = W4 + (size_t)(sec*3+1)*64*32 + h;
        float yz0[4]={},yz1[4]={},yz2[4]={},yz3[4]={};
        float yr0[4]={},yr1[4]={},yr2[4]={},yr3[4]={};
        for (int c=0;c<C;c++){
            float4 wz = Wz[c*32];
            float4 wr = Wr[c*32];
            #pragma unroll
            for (int bb=0;bb<4;bb++){
                int b = bt*4+bb;
                float x0 =sm[(0*32+b)*64+c];
                float x1r=sm[(1*32+b)*64+c];
                float x1i=sm[(2*32+b)*64+c];
                float x2 =sm[(3*32+b)*64+c];
                yz0[bb]+=x0*wz.x; yz1[bb]+=x1r*wz.y - x1i*wz.z;
                yz2[bb]+=x1r*wz.z + x1i*wz.y; yz3[bb]+=x2*wz.w;
                yr0[bb]+=x0*wr.x; yr1[bb]+=x1r*wr.y - x1i*wr.z;
                yr2[bb]+=x1r*wr.z + x1i*wr.y; yr3[bb]+=x2*wr.w;
            }
        }
        float bz[4], br[4];
        #pragma unroll
        for (int r=0;r<4;r++){ bz[r]=bias[h*4+r]; br[r]=bias[128+h*4+r]; }
        float* Z = g_Z + (size_t)sec*HSZ;
        #pragma unroll
        for (int bb=0;bb<4;bb++){
            int b = bt*4+bb;
            float vz[4] = {0.25f*(yz0[bb]+yz3[bb]+2.f*yz1[bb]), 0.25f*(yz0[bb]-yz3[bb]-2.f*yz2[bb]),
                           0.25f*(yz0[bb]+yz3[bb]-2.f*yz1[bb]), 0.25f*(yz0[bb]-yz3[bb]+2.f*yz2[bb])};
            float vr[4] = {0.25f*(yr0[bb]+yr3[bb]+2.f*yr1[bb]), 0.25f*(yr0[bb]-yr3[bb]-2.f*yr2[bb]),
                           0.25f*(yr0[bb]+yr3[bb]-2.f*yr1[bb]), 0.25f*(yr0[bb]-yr3[bb]+2.f*yr2[bb])};
            size_t hoff = (((size_t)b*Nn + n)*Hh + h)*4;
            float4 hs4 = Hs ? *reinterpret_cast<const float4*>(Hs + hoff) : make_float4(0,0,0,0);
            float hsv[4] = {hs4.x,hs4.y,hs4.z,hs4.w};
            float g[4], zv[4];
            #pragma unroll
            for (int r=0;r<4;r++){
                zv[r] = 1.f/(1.f+expf(-(vz[r] + bz[r])));
                float rg = 1.f/(1.f+expf(-(vr[r] + br[r])));
                g[r] = rg*hsv[r];
            }
            *reinterpret_cast<float4*>(Z + hoff) = make_float4(zv[0],zv[1],zv[2],zv[3]);
            size_t gb = (size_t)n*2048 + gcol + b*Hh + h;
            float s1 = g[0]-g[2], s2 = g[3]-g[1];
            g_Gf[0*GS + gb] = g[0]+g[1]+g[2]+g[3];
            g_Gf[1*GS + gb] = s1;
            g_Gf[2*GS + gb] = s2;
            g_Gf[3*GS + gb] = g[0]-g[1]+g[2]-g[3];
            g_Gf[4*GS + gb] = s1 + s2;
        }
    }
}

// Ht phase.
__device__ void htPhase(float* sm, int nItems, int secBase, int t, const float* __restrict__ Xpl,
    const float* __restrict__ HsA, const float* __restrict__ biasA,
    float* __restrict__ HnewA, float* __restrict__ outA, float* __restrict__ tailA,
    const float* __restrict__ HsB, const float* __restrict__ biasB,
    float* __restrict__ HnewB, float* __restrict__ outB, float* __restrict__ tailB)
{
    int tid = threadIdx.x;
    const size_t XS = (size_t)Tt*Nn*512;
    const size_t HSs = (size_t)Nn*2048;
    const size_t AS = (size_t)Nn*2048;
    const size_t HS2 = (size_t)NP*2048;
    float* sXx = sm;          // [4][32][32]
    float* sG  = sm + 4096;   // [4][32][32]
    for (int item = blockIdx.x; item < nItems; item += gridDim.x){
        int selB = (item >= Nn) ? 1 : 0;
        int n = item - selB*Nn;
        int sec = secBase + selB;
        const float* Hs   = selB ? HsB : HsA;
        const float* bias = selB ? biasB : biasA;
        float* Hnew = selB ? HnewB : HnewA;
        float* outp = selB ? outB : outA;
        float* tailp= selB ? tailB : tailA;
        int Fin  = sec ? 32 : 16;
        int gcol = sec ? 1024 : 0;
        int hbase= sec ? 1024 : 0;
        const float* Xrow = Xpl + (size_t)n*512;
        const float* Hrow = g_AH + (size_t)n*2048;
        const float* AGr  = g_AG + (size_t)n*2048 + gcol;
        __syncthreads();
        for (int i=tid; i<4*Fin*32; i+=256){
            int c = i % Fin; int sb = i / Fin; int s = sb >> 5; int b = sb & 31;
            const float* ptr; size_t ss;
            if (sec==0){ ptr = Xrow + b*16 + c; ss = XS; }
            else       { ptr = Hrow + b*32 + c; ss = HSs; }
            float v;
            if (s==0)      v = ptr[0];
            else if (s==1) v = ptr[ss] - ptr[2*ss];
            else if (s==2) v = ptr[4*ss] - ptr[ss] - ptr[2*ss];
            else           v = ptr[3*ss];
            sXx[(s*32 + b)*32 + c] = v;
        }
        for (int i=tid; i<4*32*32; i+=256){
            int c = i & 31; int sb = i >> 5; int s = sb >> 5; int b = sb & 31;
            const float* ptr = AGr + b*32 + c;
            float v;
            if (s==0)      v = ptr[0];
            else if (s==1) v = ptr[AS] - ptr[2*AS];
            else if (s==2) v = ptr[4*AS] - ptr[AS] - ptr[2*AS];
            else           v = ptr[3*AS];
            sG[(s*32 + b)*32 + c] = v;
        }
        __syncthreads();
        int h = tid & 31, bt = tid >> 5;
        const float4* Wh = reinterpret_cast<const float4*>(g_W) + (size_t)(sec*3+2)*64*32 + h;
        float y0[4]={},y1[4]={},y2[4]={},y3[4]={};
        for (int c=0;c<Fin;c++){
            float4 w = Wh[c*32];
            #pragma unroll
            for (int bb=0;bb<4;bb++){
                int b = bt*4+bb;
                float x0 =sXx[(0*32+b)*32+c];
                float x1r=sXx[(1*32+b)*32+c];
                float x1i=sXx[(2*32+b)*32+c];
                float x2 =sXx[(3*32+b)*32+c];
                y0[bb]+=x0*w.x; y1[bb]+=x1r*w.y - x1i*w.z;
                y2[bb]+=x1r*w.z + x1i*w.y; y3[bb]+=x2*w.w;
            }
        }
        for (int c=0;c<Hh;c++){
            float4 w = Wh[(Fin+c)*32];
            #pragma unroll
            for (int bb=0;bb<4;bb++){
                int b = bt*4+bb;
                float x0 =sG[(0*32+b)*32+c];
                float x1r=sG[(1*32+b)*32+c];
                float x1i=sG[(2*32+b)*32+c];
                float x2 =sG[(3*32+b)*32+c];
                y0[bb]+=x0*w.x; y1[bb]+=x1r*w.y - x1i*w.z;
                y2[bb]+=x1r*w.z + x1i*w.y; y3[bb]+=x2*w.w;
            }
        }
        float bh[4];
        #pragma unroll
        for (int r=0;r<4;r++) bh[r] = bias[256 + h*4 + r];
        const float* Z = g_Z + (size_t)sec*HSZ;
        #pragma unroll
        for (int bb=0;bb<4;bb++){
            int b = bt*4+bb;
            float v[4] = {0.25f*(y0[bb]+y3[bb]+2.f*y1[bb]), 0.25f*(y0[bb]-y3[bb]-2.f*y2[bb]),
                          0.25f*(y0[bb]+y3[bb]-2.f*y1[bb]), 0.25f*(y0[bb]-y3[bb]+2.f*y2[bb])};
            size_t hoff = (((size_t)b*Nn+n)*Hh + h)*4;
            float4 z4 = *reinterpret_cast<const float4*>(Z + hoff);
            float zv[4] = {z4.x,z4.y,z4.z,z4.w};
            float4 hs4 = Hs ? *reinterpret_cast<const float4*>(Hs + hoff) : make_float4(0,0,0,0);
            float hsv[4] = {hs4.x,hs4.y,hs4.z,hs4.w};
            float hn[4];
            #pragma unroll
            for (int r=0;r<4;r++){
                float ht = tanhf(v[r] + bh[r]);
                hn[r] = zv[r]*hsv[r] + (1.f-zv[r])*ht;
            }
            float4 hv = make_float4(hn[0],hn[1],hn[2],hn[3]);
            *reinterpret_cast<float4*>(Hnew + hoff) = hv;
            if (outp)
                *reinterpret_cast<float4*>(outp + (((size_t)b*Tt + t)*Nn + n)*(Hh*4) + h*4) = hv;
            if (tailp)
                *reinterpret_cast<float4*>(tailp + hoff) = hv;
            size_t hb = (size_t)n*2048 + hbase + b*Hh + h;
            float s1 = hn[0]-hn[2], s2 = hn[3]-hn[1];
            g_Hf[0*HS2 + hb] = hn[0]+hn[1]+hn[2]+hn[3];
            g_Hf[1*HS2 + hb] = s1;
            g_Hf[2*HS2 + hb] = s2;
            g_Hf[3*HS2 + hb] = hn[0]-hn[1]+hn[2]-hn[3];
            g_Hf[4*HS2 + hb] = s1 + s2;
        }
    }
}

__global__ __launch_bounds__(256, 2) void fused_kernel(
    const float* __restrict__ B0p, const float* __restrict__ B1p,
    float* __restrict__ out, float* __restrict__ tail)
{
    extern __shared__ float sm[];
    unsigned long long bar = 0;
    const unsigned long long G = gridDim.x;
    const float* AXt = g_AXt;
    float* H0r = g_H;          float* H0w = g_H + HSZ;
    float* H1r = g_H + 2*HSZ;  float* H1w = g_H + 3*HSZ;

    // ---- t = 0 ----
    gatesPhase(sm, Nn, 0, AXt, nullptr, nullptr, B0p, B0p);
    gridSync(++bar * G);
    htPhase(sm, Nn, 0, 0, AXt,
            nullptr, B0p, H0w, nullptr, nullptr,
            nullptr, B0p, H0w, nullptr, nullptr);
    gridSync(++bar * G);
    aggPhase(sm, g_Hf, g_AH, 16, 0);          // A @ fft(H0(t0))
    gridSync(++bar * G);
    gatesPhase(sm, Nn, 1, AXt, nullptr, nullptr, B1p, B1p);
    gridSync(++bar * G);
    htPhase(sm, Nn, 1, 0, AXt,
            nullptr, B1p, H1w, out, nullptr,
            nullptr, B1p, H1w, out, nullptr);
    gridSync(++bar * G);
    { float* tmp=H0r; H0r=H0w; H0w=tmp; tmp=H1r; H1r=H1w; H1w=tmp; }

    // ---- t = 1..7 ----
    for (int t=1; t<Tt; t++){
        if (t==1) aggPhase(sm, g_Hf, g_AH, 16, 1024);   // only H1 cols (H0 done at t0)
        else      aggPhase(sm, g_Hf, g_AH, 32, 0);
        gridSync(++bar * G);
        const float* Xpl = AXt + (size_t)t*Nn*512;
        gatesPhase(sm, 2*Nn, 0, Xpl, H0r, H1r, B0p, B1p);
        gridSync(++bar * G);
        aggPhase(sm, g_Gf, g_AG, 32, 0);
        gridSync(++bar * G);
        float* tl0 = (t==Tt-1 && tail) ? tail       : nullptr;
        float* tl1 = (t==Tt-1 && tail) ? tail + HSZ : nullptr;
        htPhase(sm, 2*Nn, 0, t, Xpl,
                H0r, B0p, H0w, nullptr, tl0,
                H1r, B1p, H1w, out,     tl1);
        gridSync(++bar * G);
        { float* tmp=H0r; H0r=H0w; H0w=tmp; tmp=H1r; H1r=H1w; H1w=tmp; }
    }
}

// ---------------------------------------------------------------------------
extern "C" void kernel_launch(void* const* d_in, const int* in_sizes, int n_in,
                              void* d_out, int out_size) {
    (void)in_sizes; (void)n_in;
    const float* inputs = (const float*)d_in[0];
    const float* U      = (const float*)d_in[1];
    const float* B0p    = (const float*)d_in[7];
    const float* B1p    = (const float*)d_in[13];
    float* out = (float*)d_out;
    const int OUTSZ = Bb*Tt*Nn*Hh*Rr;
    float* tail = (out_size >= OUTSZ + 2*HSZ) ? (out + OUTSZ) : nullptr;

    void* p;
    cudaGetSymbolAddress(&p, g_At);     float* Atp = (float*)p;
    cudaGetSymbolAddress(&p, g_Xf);     float* Xf  = (float*)p;
    cudaGetSymbolAddress(&p, g_Hf);     float* Hf  = (float*)p;
    cudaGetSymbolAddress(&p, g_Gf);     float* Gfp = (float*)p;
    cudaGetSymbolAddress(&p, g_AH);     float* AH  = (float*)p;
    cudaGetSymbolAddress(&p, g_AG);     float* AG  = (float*)p;
    cudaGetSymbolAddress(&p, g_barCnt); void*  bc  = p;

    cudaMemsetAsync(bc,  0, sizeof(unsigned long long));
    cudaMemsetAsync(Atp, 0, sizeof(float)*5*NP*NR);
    cudaMemsetAsync(Xf,  0, sizeof(float)*5*Tt*NP*512);
    cudaMemsetAsync(Hf,  0, sizeof(float)*5*NP*2048);
    cudaMemsetAsync(Gfp, 0, sizeof(float)*5*NP*2048);
    cudaMemsetAsync(AH,  0, sizeof(float)*5*Nn*2048);
    cudaMemsetAsync(AG,  0, sizeof(float)*5*Nn*2048);

    adj_kernel<<<Nn, 256>>>(U);
    wprep_kernel<<<48, 256>>>((const float*)d_in[2], (const float*)d_in[3], (const float*)d_in[4],
                              (const float*)d_in[5], (const float*)d_in[6],
                              (const float*)d_in[8], (const float*)d_in[9], (const float*)d_in[10],
                              (const float*)d_in[11], (const float*)d_in[12]);
    xprep_kernel<<<(Tt*Nn*512+255)/256, 256>>>(inputs);
    aggx_kernel<<<dim3(Tt*8,3,5), 256>>>();

    fused_kernel<<<GRID, 256, 32768>>>(B0p, B1p, out, tail);
}